// round 1
// baseline (speedup 1.0000x reference)
#include <cuda_runtime.h>
#include <math.h>
#include <stdint.h>

#define D_MODEL 1024
#define NUM_HEAD 16
#define T_SEQ 2048
#define BATCH 4
#define DH 64
#define QKV_SLAB (BATCH * NUM_HEAD * T_SEQ * DH)  // 8388608 floats

// Scratch for Q,K,V in (b,h,t,d) layout, 3 slabs. Static device global (no allocs).
__device__ float g_QKV[3ull * QKV_SLAB];

__device__ __forceinline__ unsigned f2tf(float x) {
    unsigned r;
    asm("cvt.rna.tf32.f32 %0, %1;" : "=r"(r) : "f"(x));
    return r;
}

__device__ __forceinline__ void mma_tf32(float d[4], const unsigned a[4],
                                         unsigned b0, unsigned b1) {
    asm volatile(
        "mma.sync.aligned.m16n8k8.row.col.f32.tf32.tf32.f32 "
        "{%0,%1,%2,%3}, {%4,%5,%6,%7}, {%8,%9}, {%0,%1,%2,%3};\n"
        : "+f"(d[0]), "+f"(d[1]), "+f"(d[2]), "+f"(d[3])
        : "r"(a[0]), "r"(a[1]), "r"(a[2]), "r"(a[3]), "r"(b0), "r"(b1));
}

// ---------------------------------------------------------------------------
// Projection: for each (b, p in {Q,K,V}):  Y[o,t] = sum_c W[o,c] * X[c,t]
// M=1024 (o), N=2048 (t), K=1024 (c). CTA tile 128x128, 8 warps (4x2),
// warp tile 32x64. TF32 mma m16n8k8. Output scattered into (b,h,t,d).
// ---------------------------------------------------------------------------
#define AS_LD 20    // 16 + 4 pad: (20*lr + lc) mod 32 all-distinct
#define BS_LD 136   // 128 + 8 pad: (8*lc + lr) mod 32 all-distinct

__global__ __launch_bounds__(256) void proj_kernel(
    const float* __restrict__ x, const float* __restrict__ Wq,
    const float* __restrict__ Wk, const float* __restrict__ Wv) {
    __shared__ float As[2][128 * AS_LD];
    __shared__ float Bs[2][16 * BS_LD];

    const int z = blockIdx.z;
    const int b = z / 3;
    const int p = z - 3 * b;
    const float* W = (p == 0) ? Wq : (p == 1) ? Wk : Wv;
    const float* xb = x + (size_t)b * D_MODEL * T_SEQ;
    float* outp = g_QKV + (size_t)p * QKV_SLAB + (size_t)b * (NUM_HEAD * T_SEQ * DH);

    const int tid = threadIdx.x;
    const int warp = tid >> 5, lane = tid & 31;
    const int wm = warp >> 1, wn = warp & 1;
    const int lr = lane >> 2, lc = lane & 3;
    const int oBase = blockIdx.y * 128, tBase = blockIdx.x * 128;

    int ar[2], ac[2], br[2], bc[2];
#pragma unroll
    for (int i = 0; i < 2; i++) {
        int f = tid + i * 256;           // 0..511 float4 slots
        ar[i] = f >> 2;                  // A: 128 rows x 4 float4
        ac[i] = (f & 3) * 4;
        br[i] = f >> 5;                  // B: 16 rows x 32 float4
        bc[i] = (f & 31) * 4;
    }

    float4 ag[2], bg[2];
#pragma unroll
    for (int i = 0; i < 2; i++) {
        ag[i] = *(const float4*)&W[(size_t)(oBase + ar[i]) * D_MODEL + ac[i]];
        bg[i] = *(const float4*)&xb[(size_t)br[i] * T_SEQ + tBase + bc[i]];
    }
#pragma unroll
    for (int i = 0; i < 2; i++) {
        *(float4*)&As[0][ar[i] * AS_LD + ac[i]] = ag[i];
        *(float4*)&Bs[0][br[i] * BS_LD + bc[i]] = bg[i];
    }
    __syncthreads();

    float acc[2][8][4];
#pragma unroll
    for (int i = 0; i < 2; i++)
#pragma unroll
        for (int j = 0; j < 8; j++)
#pragma unroll
            for (int e = 0; e < 4; e++) acc[i][j][e] = 0.f;

    for (int kc = 0; kc < 64; kc++) {
        const int cur = kc & 1;
        if (kc < 63) {
            const int k0 = (kc + 1) * 16;
#pragma unroll
            for (int i = 0; i < 2; i++) {
                ag[i] = *(const float4*)&W[(size_t)(oBase + ar[i]) * D_MODEL + k0 + ac[i]];
                bg[i] = *(const float4*)&xb[(size_t)(k0 + br[i]) * T_SEQ + tBase + bc[i]];
            }
        }
        const float* Asc = As[cur];
        const float* Bsc = Bs[cur];
#pragma unroll
        for (int ks = 0; ks < 2; ks++) {
            unsigned af[2][4];
#pragma unroll
            for (int i = 0; i < 2; i++) {
                const int rb = wm * 32 + i * 16 + lr;
                af[i][0] = f2tf(Asc[rb * AS_LD + ks * 8 + lc]);
                af[i][1] = f2tf(Asc[(rb + 8) * AS_LD + ks * 8 + lc]);
                af[i][2] = f2tf(Asc[rb * AS_LD + ks * 8 + lc + 4]);
                af[i][3] = f2tf(Asc[(rb + 8) * AS_LD + ks * 8 + lc + 4]);
            }
#pragma unroll
            for (int j = 0; j < 8; j++) {
                const int cb = wn * 64 + j * 8 + lr;
                unsigned b0 = f2tf(Bsc[(ks * 8 + lc) * BS_LD + cb]);
                unsigned b1 = f2tf(Bsc[(ks * 8 + lc + 4) * BS_LD + cb]);
                mma_tf32(acc[0][j], af[0], b0, b1);
                mma_tf32(acc[1][j], af[1], b0, b1);
            }
        }
        if (kc < 63) {
#pragma unroll
            for (int i = 0; i < 2; i++) {
                *(float4*)&As[cur ^ 1][ar[i] * AS_LD + ac[i]] = ag[i];
                *(float4*)&Bs[cur ^ 1][br[i] * BS_LD + bc[i]] = bg[i];
            }
        }
        __syncthreads();
    }

    // Epilogue: element (o, t) -> outp[(h*T + t)*64 + d], o = h*64+d
#pragma unroll
    for (int i = 0; i < 2; i++) {
#pragma unroll
        for (int j = 0; j < 8; j++) {
            const int o0 = oBase + wm * 32 + i * 16 + lr;
            const int t0 = tBase + wn * 64 + j * 8 + 2 * lc;
#pragma unroll
            for (int e = 0; e < 4; e++) {
                const int o = o0 + ((e >= 2) ? 8 : 0);
                const int t = t0 + (e & 1);
                outp[((size_t)(o >> 6) * T_SEQ + t) * DH + (o & 63)] = acc[i][j][e];
            }
        }
    }
}

// ---------------------------------------------------------------------------
// Flash attention: CTA = 64 q-rows (4 warps x 16), loop over 64-wide kv tiles.
// S = (Q/8)·K^T + b, masked, online softmax, O += P·V, epilogue divides by l
// and writes transposed (B, C, T) output.
// ---------------------------------------------------------------------------
#define KS_LD 68   // (4*lr + lc) mod 32 all-distinct for K B-frags & P A-frags
#define VS_LD 72   // (8*lc + lr) mod 32 all-distinct for V B-frags

__global__ __launch_bounds__(128) void attn_kernel(
    const float* __restrict__ mask, const float* __restrict__ bias,
    float* __restrict__ out) {
    __shared__ float Ks[64 * KS_LD];   // K tile; reused as P staging
    __shared__ float Vs[64 * VS_LD];
    __shared__ float ms[64];

    const int bh = blockIdx.y;
    const int b = bh >> 4, h = bh & 15;
    const int qb = blockIdx.x * 64;
    const int tid = threadIdx.x;
    const int warp = tid >> 5, lane = tid & 31;
    const int lr = lane >> 2, lc = lane & 3;

    const float* Qp = g_QKV + (size_t)bh * (T_SEQ * DH);
    const float* Kp = g_QKV + (size_t)QKV_SLAB + (size_t)bh * (T_SEQ * DH);
    const float* Vp = g_QKV + 2ull * QKV_SLAB + (size_t)bh * (T_SEQ * DH);
    const float bb = bias[0];

    const int q0 = qb + warp * 16 + lr;
    unsigned qa[8][4];
#pragma unroll
    for (int ks = 0; ks < 8; ks++) {
        const int c = ks * 8 + lc;
        qa[ks][0] = f2tf(0.125f * Qp[(size_t)q0 * DH + c]);
        qa[ks][1] = f2tf(0.125f * Qp[(size_t)(q0 + 8) * DH + c]);
        qa[ks][2] = f2tf(0.125f * Qp[(size_t)q0 * DH + c + 4]);
        qa[ks][3] = f2tf(0.125f * Qp[(size_t)(q0 + 8) * DH + c + 4]);
    }

    float m0 = -INFINITY, m1 = -INFINITY, l0 = 0.f, l1 = 0.f;
    float o[8][4];
#pragma unroll
    for (int nt = 0; nt < 8; nt++)
#pragma unroll
        for (int e = 0; e < 4; e++) o[nt][e] = 0.f;

    for (int it = 0; it < 32; it++) {
        const int kv0 = it * 64;
#pragma unroll
        for (int i = 0; i < 8; i++) {
            const int f = tid + i * 128;       // 1024 float4 slots: 64 rows x 16
            const int r = f >> 4, c = (f & 15) * 4;
            *(float4*)&Ks[r * KS_LD + c] = *(const float4*)&Kp[(size_t)(kv0 + r) * DH + c];
            *(float4*)&Vs[r * VS_LD + c] = *(const float4*)&Vp[(size_t)(kv0 + r) * DH + c];
        }
        if (tid < 64) ms[tid] = mask[b * T_SEQ + kv0 + tid];
        __syncthreads();

        // S = Qs · K^T  (16 x 64 per warp)
        float s[8][4];
#pragma unroll
        for (int nt = 0; nt < 8; nt++)
#pragma unroll
            for (int e = 0; e < 4; e++) s[nt][e] = 0.f;
#pragma unroll
        for (int nt = 0; nt < 8; nt++) {
#pragma unroll
            for (int ks = 0; ks < 8; ks++) {
                unsigned b0 = f2tf(Ks[(nt * 8 + lr) * KS_LD + ks * 8 + lc]);
                unsigned b1 = f2tf(Ks[(nt * 8 + lr) * KS_LD + ks * 8 + lc + 4]);
                mma_tf32(s[nt], qa[ks], b0, b1);
            }
        }

        // bias + mask (exact reference semantics), row max
        float rmax0 = -INFINITY, rmax1 = -INFINITY;
#pragma unroll
        for (int nt = 0; nt < 8; nt++) {
            const int col = nt * 8 + 2 * lc;
            const bool mk0 = ms[col] != 0.f;
            const bool mk1 = ms[col + 1] != 0.f;
            s[nt][0] = mk0 ? s[nt][0] + bb : -1e30f;
            s[nt][1] = mk1 ? s[nt][1] + bb : -1e30f;
            s[nt][2] = mk0 ? s[nt][2] + bb : -1e30f;
            s[nt][3] = mk1 ? s[nt][3] + bb : -1e30f;
            rmax0 = fmaxf(rmax0, fmaxf(s[nt][0], s[nt][1]));
            rmax1 = fmaxf(rmax1, fmaxf(s[nt][2], s[nt][3]));
        }
        rmax0 = fmaxf(rmax0, __shfl_xor_sync(0xffffffffu, rmax0, 1));
        rmax0 = fmaxf(rmax0, __shfl_xor_sync(0xffffffffu, rmax0, 2));
        rmax1 = fmaxf(rmax1, __shfl_xor_sync(0xffffffffu, rmax1, 1));
        rmax1 = fmaxf(rmax1, __shfl_xor_sync(0xffffffffu, rmax1, 2));

        const float mn0 = fmaxf(m0, rmax0), mn1 = fmaxf(m1, rmax1);
        const float sc0 = __expf(m0 - mn0), sc1 = __expf(m1 - mn1);
        m0 = mn0; m1 = mn1;

        float rs0 = 0.f, rs1 = 0.f;
#pragma unroll
        for (int nt = 0; nt < 8; nt++) {
            s[nt][0] = __expf(s[nt][0] - mn0);
            s[nt][1] = __expf(s[nt][1] - mn0);
            s[nt][2] = __expf(s[nt][2] - mn1);
            s[nt][3] = __expf(s[nt][3] - mn1);
            rs0 += s[nt][0] + s[nt][1];
            rs1 += s[nt][2] + s[nt][3];
        }
        rs0 += __shfl_xor_sync(0xffffffffu, rs0, 1);
        rs0 += __shfl_xor_sync(0xffffffffu, rs0, 2);
        rs1 += __shfl_xor_sync(0xffffffffu, rs1, 1);
        rs1 += __shfl_xor_sync(0xffffffffu, rs1, 2);
        l0 = l0 * sc0 + rs0;
        l1 = l1 * sc1 + rs1;
#pragma unroll
        for (int nt = 0; nt < 8; nt++) {
            o[nt][0] *= sc0; o[nt][1] *= sc0;
            o[nt][2] *= sc1; o[nt][3] *= sc1;
        }

        __syncthreads();  // all warps done reading Ks before P overwrites it
        float* P = Ks + warp * 16 * KS_LD;   // per-warp private 16x64 slice
#pragma unroll
        for (int nt = 0; nt < 8; nt++) {
            const int col = nt * 8 + 2 * lc;
            P[lr * KS_LD + col]           = s[nt][0];
            P[lr * KS_LD + col + 1]       = s[nt][1];
            P[(lr + 8) * KS_LD + col]     = s[nt][2];
            P[(lr + 8) * KS_LD + col + 1] = s[nt][3];
        }
        __syncwarp();

        // O += P · V
#pragma unroll
        for (int ks = 0; ks < 8; ks++) {
            unsigned pa[4];
            pa[0] = f2tf(P[lr * KS_LD + ks * 8 + lc]);
            pa[1] = f2tf(P[(lr + 8) * KS_LD + ks * 8 + lc]);
            pa[2] = f2tf(P[lr * KS_LD + ks * 8 + lc + 4]);
            pa[3] = f2tf(P[(lr + 8) * KS_LD + ks * 8 + lc + 4]);
#pragma unroll
            for (int nt = 0; nt < 8; nt++) {
                unsigned b0 = f2tf(Vs[(ks * 8 + lc) * VS_LD + nt * 8 + lr]);
                unsigned b1 = f2tf(Vs[(ks * 8 + lc + 4) * VS_LD + nt * 8 + lr]);
                mma_tf32(o[nt], pa, b0, b1);
            }
        }
        __syncthreads();  // done with Vs and P before next tile load
    }

    const float il0 = 1.f / l0, il1 = 1.f / l1;
    float* ob = out + ((size_t)b * D_MODEL + h * DH) * T_SEQ;
#pragma unroll
    for (int nt = 0; nt < 8; nt++) {
        const int ch = nt * 8 + 2 * lc;
        ob[(size_t)ch * T_SEQ + q0]           = o[nt][0] * il0;
        ob[(size_t)(ch + 1) * T_SEQ + q0]     = o[nt][1] * il0;
        ob[(size_t)ch * T_SEQ + q0 + 8]       = o[nt][2] * il1;
        ob[(size_t)(ch + 1) * T_SEQ + q0 + 8] = o[nt][3] * il1;
    }
}

extern "C" void kernel_launch(void* const* d_in, const int* in_sizes, int n_in,
                              void* d_out, int out_size) {
    const float* x    = (const float*)d_in[0];
    const float* mask = (const float*)d_in[1];
    const float* Wq   = (const float*)d_in[2];
    const float* Wk   = (const float*)d_in[3];
    const float* Wv   = (const float*)d_in[4];
    const float* bptr = (const float*)d_in[5];
    float* out = (float*)d_out;

    dim3 g1(T_SEQ / 128, D_MODEL / 128, BATCH * 3);  // (16, 8, 12)
    proj_kernel<<<g1, 256>>>(x, Wq, Wk, Wv);

    dim3 g2(T_SEQ / 64, BATCH * NUM_HEAD);           // (32, 64)
    attn_kernel<<<g2, 128>>>(mask, bptr, out);
}

// round 4
// speedup vs baseline: 1.0414x; 1.0414x over previous
#include <cuda_runtime.h>
#include <math.h>
#include <stdint.h>

#define D_MODEL 1024
#define NUM_HEAD 16
#define T_SEQ 2048
#define BATCH 4
#define DH 64
#define QKV_SLAB (BATCH * NUM_HEAD * T_SEQ * DH)  // 8388608 floats

// Scratch for Q,K,V in (b,h,t,d) layout, 3 slabs. Static device global (no allocs).
__device__ float g_QKV[3ull * QKV_SLAB];

__device__ __forceinline__ unsigned f2tf(float x) {
    unsigned r;
    asm("cvt.rna.tf32.f32 %0, %1;" : "=r"(r) : "f"(x));
    return r;
}

__device__ __forceinline__ void mma_tf32(float d[4], const unsigned a[4],
                                         unsigned b0, unsigned b1) {
    asm volatile(
        "mma.sync.aligned.m16n8k8.row.col.f32.tf32.tf32.f32 "
        "{%0,%1,%2,%3}, {%4,%5,%6,%7}, {%8,%9}, {%0,%1,%2,%3};\n"
        : "+f"(d[0]), "+f"(d[1]), "+f"(d[2]), "+f"(d[3])
        : "r"(a[0]), "r"(a[1]), "r"(a[2]), "r"(a[3]), "r"(b0), "r"(b1));
}

__device__ __forceinline__ uint4 cvt4(float4 v) {
    uint4 r;
    r.x = f2tf(v.x); r.y = f2tf(v.y); r.z = f2tf(v.z); r.w = f2tf(v.w);
    return r;
}

// ---------------------------------------------------------------------------
// Projection: for each (b, p in {Q,K,V}):  Y[o,t] = sum_c W[o,c] * X[c,t]
// M=1024 (o), N=2048 (t), K=1024 (c). CTA tile 128x128, 8 warps (4x2),
// warp tile 32x64. TF32 mma m16n8k8. Smem holds pre-converted tf32 bits.
// ---------------------------------------------------------------------------
#define AS_LD 20    // 16 + 4 pad: (20*lr + lc) mod 32 all-distinct
#define BS_LD 136   // 128 + 8 pad: (8*lc + lr) mod 32 all-distinct

__global__ __launch_bounds__(256) void proj_kernel(
    const float* __restrict__ x, const float* __restrict__ Wq,
    const float* __restrict__ Wk, const float* __restrict__ Wv) {
    __shared__ unsigned As[2][128 * AS_LD];
    __shared__ unsigned Bs[2][16 * BS_LD];

    const int z = blockIdx.z;
    const int b = z / 3;
    const int p = z - 3 * b;
    const float* W = (p == 0) ? Wq : (p == 1) ? Wk : Wv;
    const float* xb = x + (size_t)b * D_MODEL * T_SEQ;
    float* outp = g_QKV + (size_t)p * QKV_SLAB + (size_t)b * (NUM_HEAD * T_SEQ * DH);

    const int tid = threadIdx.x;
    const int warp = tid >> 5, lane = tid & 31;
    const int wm = warp >> 1, wn = warp & 1;
    const int lr = lane >> 2, lc = lane & 3;
    const int oBase = blockIdx.y * 128, tBase = blockIdx.x * 128;

    int ar[2], ac[2], br[2], bc[2];
#pragma unroll
    for (int i = 0; i < 2; i++) {
        int f = tid + i * 256;           // 0..511 float4 slots
        ar[i] = f >> 2;                  // A: 128 rows x 4 float4
        ac[i] = (f & 3) * 4;
        br[i] = f >> 5;                  // B: 16 rows x 32 float4
        bc[i] = (f & 31) * 4;
    }

    float4 ag[2], bg[2];
#pragma unroll
    for (int i = 0; i < 2; i++) {
        ag[i] = *(const float4*)&W[(size_t)(oBase + ar[i]) * D_MODEL + ac[i]];
        bg[i] = *(const float4*)&xb[(size_t)br[i] * T_SEQ + tBase + bc[i]];
    }
#pragma unroll
    for (int i = 0; i < 2; i++) {
        *(uint4*)&As[0][ar[i] * AS_LD + ac[i]] = cvt4(ag[i]);
        *(uint4*)&Bs[0][br[i] * BS_LD + bc[i]] = cvt4(bg[i]);
    }
    __syncthreads();

    float acc[2][8][4];
#pragma unroll
    for (int i = 0; i < 2; i++)
#pragma unroll
        for (int j = 0; j < 8; j++)
#pragma unroll
            for (int e = 0; e < 4; e++) acc[i][j][e] = 0.f;

    for (int kc = 0; kc < 64; kc++) {
        const int cur = kc & 1;
        if (kc < 63) {
            const int k0 = (kc + 1) * 16;
#pragma unroll
            for (int i = 0; i < 2; i++) {
                ag[i] = *(const float4*)&W[(size_t)(oBase + ar[i]) * D_MODEL + k0 + ac[i]];
                bg[i] = *(const float4*)&xb[(size_t)(k0 + br[i]) * T_SEQ + tBase + bc[i]];
            }
        }
        const unsigned* Asc = As[cur];
        const unsigned* Bsc = Bs[cur];
#pragma unroll
        for (int ks = 0; ks < 2; ks++) {
            unsigned af[2][4];
#pragma unroll
            for (int i = 0; i < 2; i++) {
                const int rb = wm * 32 + i * 16 + lr;
                af[i][0] = Asc[rb * AS_LD + ks * 8 + lc];
                af[i][1] = Asc[(rb + 8) * AS_LD + ks * 8 + lc];
                af[i][2] = Asc[rb * AS_LD + ks * 8 + lc + 4];
                af[i][3] = Asc[(rb + 8) * AS_LD + ks * 8 + lc + 4];
            }
#pragma unroll
            for (int j = 0; j < 8; j++) {
                const int cb = wn * 64 + j * 8 + lr;
                unsigned b0 = Bsc[(ks * 8 + lc) * BS_LD + cb];
                unsigned b1 = Bsc[(ks * 8 + lc + 4) * BS_LD + cb];
                mma_tf32(acc[0][j], af[0], b0, b1);
                mma_tf32(acc[1][j], af[1], b0, b1);
            }
        }
        if (kc < 63) {
#pragma unroll
            for (int i = 0; i < 2; i++) {
                *(uint4*)&As[cur ^ 1][ar[i] * AS_LD + ac[i]] = cvt4(ag[i]);
                *(uint4*)&Bs[cur ^ 1][br[i] * BS_LD + bc[i]] = cvt4(bg[i]);
            }
        }
        __syncthreads();
    }

    // Epilogue: element (o, t) -> outp[(h*T + t)*64 + d], o = h*64+d
#pragma unroll
    for (int i = 0; i < 2; i++) {
#pragma unroll
        for (int j = 0; j < 8; j++) {
            const int o0 = oBase + wm * 32 + i * 16 + lr;
            const int t0 = tBase + wn * 64 + j * 8 + 2 * lc;
#pragma unroll
            for (int e = 0; e < 4; e++) {
                const int o = o0 + ((e >= 2) ? 8 : 0);
                const int t = t0 + (e & 1);
                outp[((size_t)(o >> 6) * T_SEQ + t) * DH + (o & 63)] = acc[i][j][e];
            }
        }
    }
}

// ---------------------------------------------------------------------------
// Flash attention: CTA = 64 q-rows (4 warps x 16), loop over 64-wide kv tiles.
// K, V, P stored in smem as pre-converted tf32 bits. S = (Q/8)·K^T + b,
// masked via additive absorption, online softmax, O += P·V.
// ---------------------------------------------------------------------------
#define KS_LD 68   // (4*lr + lc) mod 32 all-distinct for K B-frags & P A-frags
#define VS_LD 72   // (8*lc + lr) mod 32 all-distinct for V B-frags

__global__ __launch_bounds__(128) void attn_kernel(
    const float* __restrict__ mask, const float* __restrict__ bias,
    float* __restrict__ out) {
    __shared__ unsigned Ks[64 * KS_LD];   // K tile (tf32 bits); reused as P staging
    __shared__ unsigned Vs[64 * VS_LD];   // V tile (tf32 bits)
    __shared__ float add_s[64];           // mask ? bias : -1e30

    const int bh = blockIdx.y;
    const int b = bh >> 4, h = bh & 15;
    const int qb = blockIdx.x * 64;
    const int tid = threadIdx.x;
    const int warp = tid >> 5, lane = tid & 31;
    const int lr = lane >> 2, lc = lane & 3;

    const float* Qp = g_QKV + (size_t)bh * (T_SEQ * DH);
    const float* Kp = g_QKV + (size_t)QKV_SLAB + (size_t)bh * (T_SEQ * DH);
    const float* Vp = g_QKV + 2ull * QKV_SLAB + (size_t)bh * (T_SEQ * DH);
    const float bb = bias[0];

    const int q0 = qb + warp * 16 + lr;
    unsigned qa[8][4];
#pragma unroll
    for (int ks = 0; ks < 8; ks++) {
        const int c = ks * 8 + lc;
        qa[ks][0] = f2tf(0.125f * Qp[(size_t)q0 * DH + c]);
        qa[ks][1] = f2tf(0.125f * Qp[(size_t)(q0 + 8) * DH + c]);
        qa[ks][2] = f2tf(0.125f * Qp[(size_t)q0 * DH + c + 4]);
        qa[ks][3] = f2tf(0.125f * Qp[(size_t)(q0 + 8) * DH + c + 4]);
    }

    float m0 = -INFINITY, m1 = -INFINITY, l0 = 0.f, l1 = 0.f;
    float o[8][4];
#pragma unroll
    for (int nt = 0; nt < 8; nt++)
#pragma unroll
        for (int e = 0; e < 4; e++) o[nt][e] = 0.f;

    for (int it = 0; it < 32; it++) {
        const int kv0 = it * 64;
#pragma unroll
        for (int i = 0; i < 8; i++) {
            const int f = tid + i * 128;       // 1024 float4 slots: 64 rows x 16
            const int r = f >> 4, c = (f & 15) * 4;
            *(uint4*)&Ks[r * KS_LD + c] = cvt4(*(const float4*)&Kp[(size_t)(kv0 + r) * DH + c]);
            *(uint4*)&Vs[r * VS_LD + c] = cvt4(*(const float4*)&Vp[(size_t)(kv0 + r) * DH + c]);
        }
        if (tid < 64) {
            const float mv = mask[b * T_SEQ + kv0 + tid];
            add_s[tid] = (mv != 0.f) ? bb : -1e30f;
        }
        __syncthreads();

        // S = Qs · K^T  (16 x 64 per warp)
        float s[8][4];
#pragma unroll
        for (int nt = 0; nt < 8; nt++)
#pragma unroll
            for (int e = 0; e < 4; e++) s[nt][e] = 0.f;
#pragma unroll
        for (int nt = 0; nt < 8; nt++) {
#pragma unroll
            for (int ks = 0; ks < 8; ks++) {
                unsigned b0 = Ks[(nt * 8 + lr) * KS_LD + ks * 8 + lc];
                unsigned b1 = Ks[(nt * 8 + lr) * KS_LD + ks * 8 + lc + 4];
                mma_tf32(s[nt], qa[ks], b0, b1);
            }
        }

        // bias+mask via additive absorption (s + -1e30 == -1e30 exactly), row max
        float rmax0 = -INFINITY, rmax1 = -INFINITY;
#pragma unroll
        for (int nt = 0; nt < 8; nt++) {
            const int col = nt * 8 + 2 * lc;
            const float2 ad = *(const float2*)&add_s[col];
            s[nt][0] += ad.x;
            s[nt][1] += ad.y;
            s[nt][2] += ad.x;
            s[nt][3] += ad.y;
            rmax0 = fmaxf(rmax0, fmaxf(s[nt][0], s[nt][1]));
            rmax1 = fmaxf(rmax1, fmaxf(s[nt][2], s[nt][3]));
        }
        rmax0 = fmaxf(rmax0, __shfl_xor_sync(0xffffffffu, rmax0, 1));
        rmax0 = fmaxf(rmax0, __shfl_xor_sync(0xffffffffu, rmax0, 2));
        rmax1 = fmaxf(rmax1, __shfl_xor_sync(0xffffffffu, rmax1, 1));
        rmax1 = fmaxf(rmax1, __shfl_xor_sync(0xffffffffu, rmax1, 2));

        const float mn0 = fmaxf(m0, rmax0), mn1 = fmaxf(m1, rmax1);
        const float sc0 = __expf(m0 - mn0), sc1 = __expf(m1 - mn1);
        m0 = mn0; m1 = mn1;

        float rs0 = 0.f, rs1 = 0.f;
#pragma unroll
        for (int nt = 0; nt < 8; nt++) {
            s[nt][0] = __expf(s[nt][0] - mn0);
            s[nt][1] = __expf(s[nt][1] - mn0);
            s[nt][2] = __expf(s[nt][2] - mn1);
            s[nt][3] = __expf(s[nt][3] - mn1);
            rs0 += s[nt][0] + s[nt][1];
            rs1 += s[nt][2] + s[nt][3];
        }
        rs0 += __shfl_xor_sync(0xffffffffu, rs0, 1);
        rs0 += __shfl_xor_sync(0xffffffffu, rs0, 2);
        rs1 += __shfl_xor_sync(0xffffffffu, rs1, 1);
        rs1 += __shfl_xor_sync(0xffffffffu, rs1, 2);
        l0 = l0 * sc0 + rs0;
        l1 = l1 * sc1 + rs1;
#pragma unroll
        for (int nt = 0; nt < 8; nt++) {
            o[nt][0] *= sc0; o[nt][1] *= sc0;
            o[nt][2] *= sc1; o[nt][3] *= sc1;
        }

        __syncthreads();  // all warps done reading Ks before P overwrites it
        unsigned* P = Ks + warp * 16 * KS_LD;   // per-warp private 16x64 slice
#pragma unroll
        for (int nt = 0; nt < 8; nt++) {
            const int col = nt * 8 + 2 * lc;
            P[lr * KS_LD + col]           = f2tf(s[nt][0]);
            P[lr * KS_LD + col + 1]       = f2tf(s[nt][1]);
            P[(lr + 8) * KS_LD + col]     = f2tf(s[nt][2]);
            P[(lr + 8) * KS_LD + col + 1] = f2tf(s[nt][3]);
        }
        __syncwarp();

        // O += P · V
#pragma unroll
        for (int ks = 0; ks < 8; ks++) {
            unsigned pa[4];
            pa[0] = P[lr * KS_LD + ks * 8 + lc];
            pa[1] = P[(lr + 8) * KS_LD + ks * 8 + lc];
            pa[2] = P[lr * KS_LD + ks * 8 + lc + 4];
            pa[3] = P[(lr + 8) * KS_LD + ks * 8 + lc + 4];
#pragma unroll
            for (int nt = 0; nt < 8; nt++) {
                unsigned b0 = Vs[(ks * 8 + lc) * VS_LD + nt * 8 + lr];
                unsigned b1 = Vs[(ks * 8 + lc + 4) * VS_LD + nt * 8 + lr];
                mma_tf32(o[nt], pa, b0, b1);
            }
        }
        __syncthreads();  // done with Vs and P before next tile load
    }

    const float il0 = 1.f / l0, il1 = 1.f / l1;
    float* ob = out + ((size_t)b * D_MODEL + h * DH) * T_SEQ;
#pragma unroll
    for (int nt = 0; nt < 8; nt++) {
        const int ch = nt * 8 + 2 * lc;
        ob[(size_t)ch * T_SEQ + q0]           = o[nt][0] * il0;
        ob[(size_t)(ch + 1) * T_SEQ + q0]     = o[nt][1] * il0;
        ob[(size_t)ch * T_SEQ + q0 + 8]       = o[nt][2] * il1;
        ob[(size_t)(ch + 1) * T_SEQ + q0 + 8] = o[nt][3] * il1;
    }
}

extern "C" void kernel_launch(void* const* d_in, const int* in_sizes, int n_in,
                              void* d_out, int out_size) {
    const float* x    = (const float*)d_in[0];
    const float* mask = (const float*)d_in[1];
    const float* Wq   = (const float*)d_in[2];
    const float* Wk   = (const float*)d_in[3];
    const float* Wv   = (const float*)d_in[4];
    const float* bptr = (const float*)d_in[5];
    float* out = (float*)d_out;

    dim3 g1(T_SEQ / 128, D_MODEL / 128, BATCH * 3);  // (16, 8, 12)
    proj_kernel<<<g1, 256>>>(x, Wq, Wk, Wv);

    dim3 g2(T_SEQ / 64, BATCH * NUM_HEAD);           // (32, 64)
    attn_kernel<<<g2, 128>>>(mask, bptr, out);
}